// round 13
// baseline (speedup 1.0000x reference)
#include <cuda_runtime.h>
#include <cuda_fp16.h>
#include <math.h>
#include <stdint.h>

#define Bsz 4
#define Lseq 2048
#define Dmodel 1024
#define Hheads 16
#define DffDim 4096
#define MAXDIST 512
#define HDdim 64
#define Mrows (Bsz*Lseq)

// Scratch (allocation-free rule: __device__ globals)
__device__ __half h_x   [Mrows*Dmodel];
__device__ __half h_wqkv[Dmodel*3*Dmodel];
__device__ __half h_wout[Dmodel*Dmodel];
__device__ __half h_wff1[Dmodel*DffDim];
__device__ __half h_wff2[DffDim*Dmodel];
__device__ __half h_qkv [Mrows*3*Dmodel];
__device__ __half h_ctx [Mrows*Dmodel];
__device__ __half h_x1  [Mrows*Dmodel];
__device__ __half h_hb  [Mrows*DffDim];
__device__ __half h_tmp [Mrows*Dmodel];

// ---------------------------------------------------------------------------
__device__ __forceinline__ uint32_t s2u(const void* p) {
    uint32_t a;
    asm("{ .reg .u64 t; cvta.to.shared.u64 t, %1; cvt.u32.u64 %0, t; }"
        : "=r"(a) : "l"(p));
    return a;
}
__device__ __forceinline__ void ldsm4(uint32_t* r, uint32_t a) {
    asm volatile("ldmatrix.sync.aligned.m8n8.x4.shared.b16 {%0,%1,%2,%3}, [%4];"
                 : "=r"(r[0]), "=r"(r[1]), "=r"(r[2]), "=r"(r[3]) : "r"(a));
}
__device__ __forceinline__ void ldsm4t(uint32_t* r, uint32_t a) {
    asm volatile("ldmatrix.sync.aligned.m8n8.x4.trans.shared.b16 {%0,%1,%2,%3}, [%4];"
                 : "=r"(r[0]), "=r"(r[1]), "=r"(r[2]), "=r"(r[3]) : "r"(a));
}
__device__ __forceinline__ void mma16(float* c, const uint32_t* a,
                                      uint32_t b0, uint32_t b1) {
    asm volatile(
        "mma.sync.aligned.m16n8k16.row.col.f32.f16.f16.f32 "
        "{%0,%1,%2,%3}, {%4,%5,%6,%7}, {%8,%9}, {%0,%1,%2,%3};"
        : "+f"(c[0]), "+f"(c[1]), "+f"(c[2]), "+f"(c[3])
        : "r"(a[0]), "r"(a[1]), "r"(a[2]), "r"(a[3]), "r"(b0), "r"(b1));
}
#define CPA16(dst, src) \
    asm volatile("cp.async.cg.shared.global [%0], [%1], 16;" :: "r"(dst), "l"(src))
#define CPA_COMMIT() asm volatile("cp.async.commit_group;")

// exact GELU via single-poly erff
__device__ __forceinline__ float gelu_f(float v) {
    return 0.5f * v * (1.f + erff(v * 0.70710678118654752f));
}

// ---------------------------------------------------------------------------
// Fused fp32 -> fp16 conversion of x + 4 weight matrices (one launch).
// ---------------------------------------------------------------------------
#define CN0 (Mrows*Dmodel/4)
#define CN1 (Dmodel*3*Dmodel/4)
#define CN2 (Dmodel*Dmodel/4)
#define CN3 (Dmodel*DffDim/4)
#define CN4 (DffDim*Dmodel/4)
#define CNT (CN0+CN1+CN2+CN3+CN4)

__global__ void cvt_all(const float4* __restrict__ a0, __half2* __restrict__ d0,
                        const float4* __restrict__ a1, __half2* __restrict__ d1,
                        const float4* __restrict__ a2, __half2* __restrict__ d2,
                        const float4* __restrict__ a3, __half2* __restrict__ d3,
                        const float4* __restrict__ a4, __half2* __restrict__ d4)
{
    int j = blockIdx.x*256 + threadIdx.x;
    const float4* s; __half2* d;
    if (j < CN0) { s = a0; d = d0; }
    else { j -= CN0;
    if (j < CN1) { s = a1; d = d1; }
    else { j -= CN1;
    if (j < CN2) { s = a2; d = d2; }
    else { j -= CN2;
    if (j < CN3) { s = a3; d = d3; }
    else { j -= CN3; s = a4; d = d4; } } } }
    float4 v = s[j];
    d[2*j  ] = __floats2half2_rn(v.x, v.y);
    d[2*j+1] = __floats2half2_rn(v.z, v.w);
}

// ---------------------------------------------------------------------------
// fp16 tensor-core GEMM: 128x128x64 tile, 8 warps (2m x 4n), warp 64x32,
// ldmatrix + m16n8k16, 3-stage cp.async, 2 CTA/SM, ONE sync per kt,
// register-double-buffered fragments (af per-ks, bf per-p) so each LDSM
// has >= 8 mmas of latency cover.
// EPI: 0 none, 1 +bias(f32)+res(fp16), 2 +bias then exact GELU.
// OUTH: 1 -> fp16 out, 0 -> fp32 out.
// ---------------------------------------------------------------------------
#define G_SMEM (3*32768)

template<int EPI, int OUTH>
__global__ __launch_bounds__(256, 2)
void gemm_f16(const __half* __restrict__ A, const __half* __restrict__ B,
              float* __restrict__ Cf, __half* __restrict__ Ch,
              int M, int N, int K,
              const float* __restrict__ bias, const __half* __restrict__ res)
{
    extern __shared__ char smem[];
    const uint32_t sb = s2u(smem);
    const int tid = threadIdx.x, wid = tid >> 5, lane = tid & 31;
    const int m0 = blockIdx.y*128, n0 = blockIdx.x*128;
    const int KT = K >> 6;
    const int wm = (wid & 1)*64, wn = (wid >> 1)*32;
    const int r = lane >> 2, cc = lane & 3;
    const int l7 = lane & 7, l15 = lane & 15, lh = lane >> 4;
    const int cbb = (wn >> 3);   // B chunk base for this warp

    auto loadAB = [&](int kt, int s) {
        const uint32_t stA = sb + s*32768;
        const uint32_t stB = stA + 16384;
#pragma unroll
        for (int i = 0; i < 4; i++) {
            int idx = tid + i*256;
            int row = idx >> 3, ch = idx & 7;
            CPA16(stA + row*128 + ((ch ^ (row & 7)) << 4),
                  A + (size_t)(m0 + row)*K + kt*64 + ch*8);
        }
#pragma unroll
        for (int i = 0; i < 4; i++) {
            int idx = tid + i*256;
            int k = idx >> 4, ch = idx & 15;
            CPA16(stB + k*256 + ((ch ^ (k & 7)) << 4),
                  B + (size_t)(kt*64 + k)*N + n0 + ch*8);
        }
    };

    float acc[4][4][4];
#pragma unroll
    for (int mi = 0; mi < 4; mi++)
#pragma unroll
        for (int ni = 0; ni < 4; ni++)
#pragma unroll
            for (int q = 0; q < 4; q++) acc[mi][ni][q] = 0.f;

    loadAB(0, 0); CPA_COMMIT();
    loadAB(1, 1); CPA_COMMIT();

    for (int kt = 0; kt < KT; kt++) {
        // leading sync covers RAW (stage kt ready) and WAR (stage (kt+2)%3 free)
        if (kt + 1 < KT) asm volatile("cp.async.wait_group 1;");
        else             asm volatile("cp.async.wait_group 0;");
        __syncthreads();

        if (kt + 2 < KT) {
            loadAB(kt + 2, (kt + 2) % 3);
            CPA_COMMIT();
        }

        const uint32_t stA = sb + (kt % 3)*32768;
        const uint32_t stB = stA + 16384;
        const int arow = wm + l15;
        const uint32_t aBase = stA + arow*128;
        const uint32_t bRow  = stB + l15*256;

        uint32_t afA[4][4], afB[4][4], bfc[4], bfn[4];
        // preload ks=0 fragments
#pragma unroll
        for (int mi = 0; mi < 4; mi++)
            ldsm4(afA[mi], aBase + mi*16*128 + (((lh) ^ l7) << 4));
        ldsm4t(bfc, bRow + (((cbb + lh) ^ l7) << 4));

#pragma unroll
        for (int ks = 0; ks < 4; ks++) {
            uint32_t (*cur)[4] = (ks & 1) ? afB : afA;
            uint32_t (*nxt)[4] = (ks & 1) ? afA : afB;
            // prefetch af for ks+1 (covered by this ks's 16 mmas)
            if (ks < 3) {
#pragma unroll
                for (int mi = 0; mi < 4; mi++)
                    ldsm4(nxt[mi], aBase + mi*16*128 + ((((ks+1)*2 + lh) ^ l7) << 4));
            }
            // p = 0: prefetch p=1's bf, mma with bfc
            ldsm4t(bfn, bRow + ks*16*256 + (((cbb + 2 + lh) ^ l7) << 4));
#pragma unroll
            for (int mi = 0; mi < 4; mi++) {
                mma16(acc[mi][0], cur[mi], bfc[0], bfc[1]);
                mma16(acc[mi][1], cur[mi], bfc[2], bfc[3]);
            }
            // p = 1: prefetch next ks's p=0 bf, mma with bfn
            if (ks < 3)
                ldsm4t(bfc, bRow + (ks+1)*16*256 + (((cbb + lh) ^ l7) << 4));
#pragma unroll
            for (int mi = 0; mi < 4; mi++) {
                mma16(acc[mi][2], cur[mi], bfn[0], bfn[1]);
                mma16(acc[mi][3], cur[mi], bfn[2], bfn[3]);
            }
        }
    }

    // Epilogue (registers only)
#pragma unroll
    for (int ni = 0; ni < 4; ni++) {
        const int col = n0 + wn + ni*8 + 2*cc;
        float b0 = 0.f, b1 = 0.f;
        if (EPI != 0) { b0 = bias[col]; b1 = bias[col + 1]; }
#pragma unroll
        for (int mi = 0; mi < 4; mi++) {
#pragma unroll
            for (int hh = 0; hh < 2; hh++) {
                const int rr = m0 + wm + mi*16 + r + hh*8;
                float v0 = acc[mi][ni][2*hh    ];
                float v1 = acc[mi][ni][2*hh + 1];
                if (EPI != 0) { v0 += b0; v1 += b1; }
                if (EPI == 1) {
                    float2 rv = __half22float2(
                        *(const __half2*)&res[(size_t)rr*N + col]);
                    v0 += rv.x; v1 += rv.y;
                }
                if (EPI == 2) {
                    v0 = gelu_f(v0);
                    v1 = gelu_f(v1);
                }
                if (OUTH)
                    *(__half2*)&Ch[(size_t)rr*N + col] = __floats2half2_rn(v0, v1);
                else
                    *(float2*)&Cf[(size_t)rr*N + col] = make_float2(v0, v1);
            }
        }
    }
}

// ---------------------------------------------------------------------------
// fp16 flash attention (unchanged): 256 thr / 8 warps, 128-row Q tile,
// double-buffered cp.async KV, fp32 online softmax.
// ---------------------------------------------------------------------------
#define FA_SMEM (68*1024)

__global__ __launch_bounds__(256)
void flash_attn_f16(const __half* __restrict__ qkv,
                    const float* __restrict__ bias_table,
                    __half* __restrict__ ctx)
{
    extern __shared__ char smem[];
    const uint32_t Qb = s2u(smem);
    const uint32_t Kb0 = Qb + 16384;
    const uint32_t Vb0 = Qb + 32768;
    const uint32_t Pb  = Qb + 49152;
    float* Bias = (float*)(smem + 65536);

    const int qt = blockIdx.x, bh = blockIdx.y;
    const int b = bh >> 4, h = bh & 15;
    const int tid = threadIdx.x;
    const int wid = tid >> 5, lane = tid & 31;
    const int r = lane >> 2, cc = lane & 3;
    const int l7 = lane & 7, l15 = lane & 15, lh = lane >> 4;
    const int q0 = qt*128, wr = wid*16;
    const size_t rs = 3*Dmodel;
    const __half* base = qkv + (size_t)(b*Lseq)*rs + h*HDdim;

    for (int i = tid; i < 2*MAXDIST-1; i += 256)
        Bias[i] = __ldg(&bias_table[(size_t)i*Hheads + h]);

#pragma unroll
    for (int i = 0; i < 4; i++) {
        int idx = tid + i*256;
        int row = idx >> 3, ch = idx & 7;
        CPA16(Qb + row*128 + ((ch ^ (row & 7)) << 4),
              base + (size_t)(q0 + row)*rs + ch*8);
    }
    CPA_COMMIT();

    auto loadKV = [&](int kt, int s) {
        const int k0 = kt*64;
        const uint32_t Kb = Kb0 + s*8192;
        const uint32_t Vb = Vb0 + s*8192;
#pragma unroll
        for (int i = 0; i < 2; i++) {
            int idx = tid + i*256;
            int row = idx >> 3, ch = idx & 7;
            const __half* gk = base + (size_t)(k0 + row)*rs + Dmodel + ch*8;
            uint32_t sw = ((ch ^ (row & 7)) << 4);
            CPA16(Kb + row*128 + sw, gk);
            CPA16(Vb + row*128 + sw, gk + Dmodel);
        }
    };

    loadKV(0, 0);
    CPA_COMMIT();
    asm volatile("cp.async.wait_group 1;");
    __syncthreads();

    uint32_t qa[4][4];
#pragma unroll
    for (int ks = 0; ks < 4; ks++) {
        int row = wr + l15;
        ldsm4(qa[ks], Qb + row*128 + (((ks*2 + lh) ^ l7) << 4));
    }

    float oacc[8][4];
#pragma unroll
    for (int nt = 0; nt < 8; nt++)
#pragma unroll
        for (int q = 0; q < 4; q++) oacc[nt][q] = 0.f;
    float m0v = -1e30f, m1v = -1e30f, l0 = 0.f, l1 = 0.f;
    const float scale = 0.125f;
    const int qg0 = q0 + wr + r, qg1 = qg0 + 8;
    const int KT = Lseq/64;

    for (int kt = 0; kt < KT; kt++) {
        const int s = kt & 1;
        if (kt + 1 < KT) {
            loadKV(kt + 1, s ^ 1);
            CPA_COMMIT();
            asm volatile("cp.async.wait_group 1;");
        } else {
            asm volatile("cp.async.wait_group 0;");
        }
        __syncthreads();

        const uint32_t Kb = Kb0 + s*8192;
        const uint32_t Vb = Vb0 + s*8192;
        const int k0 = kt*64;

        float sacc[8][4];
#pragma unroll
        for (int nt = 0; nt < 8; nt++)
#pragma unroll
            for (int q = 0; q < 4; q++) sacc[nt][q] = 0.f;
#pragma unroll
        for (int ks = 0; ks < 4; ks++) {
#pragma unroll
            for (int np = 0; np < 4; np++) {
                int key = (np*2 + lh)*8 + l7;
                int ch = ks*2 + ((lane >> 3) & 1);
                uint32_t bf[4];
                ldsm4(bf, Kb + key*128 + ((ch ^ l7) << 4));
                mma16(sacc[2*np  ], qa[ks], bf[0], bf[1]);
                mma16(sacc[2*np+1], qa[ks], bf[2], bf[3]);
            }
        }

        float rmax0 = -1e30f, rmax1 = -1e30f;
#pragma unroll
        for (int nt = 0; nt < 8; nt++) {
            const int kg = k0 + nt*8 + 2*cc;
            int i00 = min(max(kg     - qg0 + (MAXDIST-1), 0), 2*MAXDIST-2);
            int i01 = min(max(kg + 1 - qg0 + (MAXDIST-1), 0), 2*MAXDIST-2);
            int i10 = min(max(kg     - qg1 + (MAXDIST-1), 0), 2*MAXDIST-2);
            int i11 = min(max(kg + 1 - qg1 + (MAXDIST-1), 0), 2*MAXDIST-2);
            sacc[nt][0] = fmaf(sacc[nt][0], scale, Bias[i00]);
            sacc[nt][1] = fmaf(sacc[nt][1], scale, Bias[i01]);
            sacc[nt][2] = fmaf(sacc[nt][2], scale, Bias[i10]);
            sacc[nt][3] = fmaf(sacc[nt][3], scale, Bias[i11]);
            rmax0 = fmaxf(rmax0, fmaxf(sacc[nt][0], sacc[nt][1]));
            rmax1 = fmaxf(rmax1, fmaxf(sacc[nt][2], sacc[nt][3]));
        }
#pragma unroll
        for (int o = 1; o <= 2; o <<= 1) {
            rmax0 = fmaxf(rmax0, __shfl_xor_sync(0xffffffffu, rmax0, o));
            rmax1 = fmaxf(rmax1, __shfl_xor_sync(0xffffffffu, rmax1, o));
        }
        const float mn0 = fmaxf(m0v, rmax0);
        const float mn1 = fmaxf(m1v, rmax1);
        const float corr0 = __expf(m0v - mn0);
        const float corr1 = __expf(m1v - mn1);
        m0v = mn0; m1v = mn1;

        float rsum0 = 0.f, rsum1 = 0.f;
#pragma unroll
        for (int nt = 0; nt < 8; nt++) {
            float p00 = __expf(sacc[nt][0] - mn0);
            float p01 = __expf(sacc[nt][1] - mn0);
            float p10 = __expf(sacc[nt][2] - mn1);
            float p11 = __expf(sacc[nt][3] - mn1);
            rsum0 += p00 + p01;
            rsum1 += p10 + p11;
            uint32_t sw = ((nt ^ r) << 4) + 4*cc;
            *(__half2*)(smem + (Pb - Qb) + (wr + r    )*128 + sw) = __floats2half2_rn(p00, p01);
            *(__half2*)(smem + (Pb - Qb) + (wr + r + 8)*128 + sw) = __floats2half2_rn(p10, p11);
        }
#pragma unroll
        for (int o = 1; o <= 2; o <<= 1) {
            rsum0 += __shfl_xor_sync(0xffffffffu, rsum0, o);
            rsum1 += __shfl_xor_sync(0xffffffffu, rsum1, o);
        }
        l0 = l0*corr0 + rsum0;
        l1 = l1*corr1 + rsum1;
#pragma unroll
        for (int nt = 0; nt < 8; nt++) {
            oacc[nt][0] *= corr0; oacc[nt][1] *= corr0;
            oacc[nt][2] *= corr1; oacc[nt][3] *= corr1;
        }
        __syncwarp();

#pragma unroll
        for (int ks = 0; ks < 4; ks++) {
            uint32_t pf[4];
            {
                int row = wr + l15;
                ldsm4(pf, Pb + row*128 + (((ks*2 + lh) ^ l7) << 4));
            }
#pragma unroll
            for (int p = 0; p < 4; p++) {
                int kk = ks*16 + l15;
                int ch = p*2 + lh;
                uint32_t bf[4];
                ldsm4t(bf, Vb + kk*128 + ((ch ^ l7) << 4));
                mma16(oacc[2*p  ], pf, bf[0], bf[1]);
                mma16(oacc[2*p+1], pf, bf[2], bf[3]);
            }
        }
        __syncthreads();
    }

    const float inv0 = 1.f / l0;
    const float inv1 = 1.f / l1;
    __half* c0p = ctx + (size_t)(b*Lseq + qg0)*Dmodel + h*HDdim;
    __half* c1p = ctx + (size_t)(b*Lseq + qg1)*Dmodel + h*HDdim;
#pragma unroll
    for (int nt = 0; nt < 8; nt++) {
        const int col = nt*8 + 2*cc;
        *(__half2*)&c0p[col] = __floats2half2_rn(oacc[nt][0]*inv0, oacc[nt][1]*inv0);
        *(__half2*)&c1p[col] = __floats2half2_rn(oacc[nt][2]*inv1, oacc[nt][3]*inv1);
    }
}

// ---------------------------------------------------------------------------
// LayerNorm over rows of 1024, fp16 input; optional fp32 and fp16 outputs.
// ---------------------------------------------------------------------------
__global__ __launch_bounds__(256)
void ln_kernel(const __half* __restrict__ in, const float* __restrict__ gamma,
               const float* __restrict__ beta, float* __restrict__ outf,
               __half* __restrict__ out16)
{
    __shared__ float red[16];
    const int row = blockIdx.x;
    const int tid = threadIdx.x;
    const __half2* ip = (const __half2*)(in + (size_t)row*Dmodel);
    float2 fa = __half22float2(ip[2*tid]);
    float2 fb = __half22float2(ip[2*tid+1]);
    float s  = fa.x + fa.y + fb.x + fb.y;
    float sq = fa.x*fa.x + fa.y*fa.y + fb.x*fb.x + fb.y*fb.y;
#pragma unroll
    for (int o = 16; o >= 1; o >>= 1) {
        s  += __shfl_xor_sync(0xffffffffu, s,  o);
        sq += __shfl_xor_sync(0xffffffffu, sq, o);
    }
    const int wid = tid >> 5, lane = tid & 31;
    if (lane == 0) { red[wid] = s; red[wid+8] = sq; }
    __syncthreads();
    if (tid < 32) {
        float s2 = (lane < 8) ? red[lane]   : 0.f;
        float q2 = (lane < 8) ? red[lane+8] : 0.f;
#pragma unroll
        for (int o = 4; o >= 1; o >>= 1) {
            s2 += __shfl_xor_sync(0xffffffffu, s2, o);
            q2 += __shfl_xor_sync(0xffffffffu, q2, o);
        }
        if (lane == 0) { red[0] = s2; red[1] = q2; }
    }
    __syncthreads();
    const float mu  = red[0] * (1.f/Dmodel);
    const float var = red[1] * (1.f/Dmodel) - mu*mu;
    const float inv = rsqrtf(var + 1e-5f);
    const float4 g  = ((const float4*)gamma)[tid];
    const float4 be = ((const float4*)beta)[tid];
    float4 o;
    o.x = (fa.x - mu)*inv*g.x + be.x;
    o.y = (fa.y - mu)*inv*g.y + be.y;
    o.z = (fb.x - mu)*inv*g.z + be.z;
    o.w = (fb.y - mu)*inv*g.w + be.w;
    if (outf)
        ((float4*)(outf + (size_t)row*Dmodel))[tid] = o;
    if (out16) {
        __half2* o2 = (__half2*)(out16 + (size_t)row*Dmodel);
        o2[2*tid  ] = __floats2half2_rn(o.x, o.y);
        o2[2*tid+1] = __floats2half2_rn(o.z, o.w);
    }
}

// ---------------------------------------------------------------------------
extern "C" void kernel_launch(void* const* d_in, const int* in_sizes, int n_in,
                              void* d_out, int out_size)
{
    const float* x          = (const float*)d_in[0];
    const float* w_qkv      = (const float*)d_in[1];
    const float* w_out      = (const float*)d_in[2];
    const float* b_out      = (const float*)d_in[3];
    const float* bias_table = (const float*)d_in[4];
    const float* gamma1     = (const float*)d_in[5];
    const float* beta1      = (const float*)d_in[6];
    const float* w_ff1      = (const float*)d_in[7];
    const float* b_ff1      = (const float*)d_in[8];
    const float* w_ff2      = (const float*)d_in[9];
    const float* b_ff2      = (const float*)d_in[10];
    const float* gamma2     = (const float*)d_in[11];
    const float* beta2      = (const float*)d_in[12];
    float* out = (float*)d_out;

    __half *hx, *hwqkv, *hwout, *hwff1, *hwff2, *hqkv, *hctx, *hx1, *hhb, *htmp;
    cudaGetSymbolAddress((void**)&hx,    h_x);
    cudaGetSymbolAddress((void**)&hwqkv, h_wqkv);
    cudaGetSymbolAddress((void**)&hwout, h_wout);
    cudaGetSymbolAddress((void**)&hwff1, h_wff1);
    cudaGetSymbolAddress((void**)&hwff2, h_wff2);
    cudaGetSymbolAddress((void**)&hqkv,  h_qkv);
    cudaGetSymbolAddress((void**)&hctx,  h_ctx);
    cudaGetSymbolAddress((void**)&hx1,   h_x1);
    cudaGetSymbolAddress((void**)&hhb,   h_hb);
    cudaGetSymbolAddress((void**)&htmp,  h_tmp);

    cudaFuncSetAttribute(gemm_f16<0,1>,
                         cudaFuncAttributeMaxDynamicSharedMemorySize, G_SMEM);
    cudaFuncSetAttribute(gemm_f16<1,1>,
                         cudaFuncAttributeMaxDynamicSharedMemorySize, G_SMEM);
    cudaFuncSetAttribute(gemm_f16<2,1>,
                         cudaFuncAttributeMaxDynamicSharedMemorySize, G_SMEM);
    cudaFuncSetAttribute(flash_attn_f16,
                         cudaFuncAttributeMaxDynamicSharedMemorySize, FA_SMEM);

    const int M = Mrows;  // 8192

    // 0. all fp32->fp16 conversions, one launch
    cvt_all<<<CNT/256, 256>>>(
        (const float4*)x,     (__half2*)hx,
        (const float4*)w_qkv, (__half2*)hwqkv,
        (const float4*)w_out, (__half2*)hwout,
        (const float4*)w_ff1, (__half2*)hwff1,
        (const float4*)w_ff2, (__half2*)hwff2);

    // 1. qkv = x @ w_qkv  (fp16 out)
    gemm_f16<0,1><<<dim3(3*Dmodel/128, M/128), 256, G_SMEM>>>(
        hx, hwqkv, nullptr, hqkv, M, 3*Dmodel, Dmodel, nullptr, nullptr);

    // 2. attention -> ctx (fp16)
    flash_attn_f16<<<dim3(Lseq/128, Bsz*Hheads), 256, FA_SMEM>>>(
        hqkv, bias_table, hctx);

    // 3. tmp = ctx @ w_out + b_out + x  (fp16 out, fp16 res)
    gemm_f16<1,1><<<dim3(Dmodel/128, M/128), 256, G_SMEM>>>(
        hctx, hwout, nullptr, htmp, M, Dmodel, Dmodel, b_out, hx);

    // 4. x1 = LN(tmp)  (fp16 out only)
    ln_kernel<<<M, 256>>>(htmp, gamma1, beta1, nullptr, hx1);

    // 5. hb = GELU(x1 @ w_ff1 + b_ff1)  (fp16 out)
    gemm_f16<2,1><<<dim3(DffDim/128, M/128), 256, G_SMEM>>>(
        hx1, hwff1, nullptr, hhb, M, DffDim, Dmodel, b_ff1, nullptr);

    // 6. tmp = hb @ w_ff2 + b_ff2 + x1  (fp16 out, fp16 res)
    gemm_f16<1,1><<<dim3(Dmodel/128, M/128), 256, G_SMEM>>>(
        hhb, hwff2, nullptr, htmp, M, Dmodel, DffDim, b_ff2, hx1);

    // 7. out = LN(tmp)  (fp32 out)
    ln_kernel<<<M, 256>>>(htmp, gamma2, beta2, out, nullptr);
}

// round 14
// speedup vs baseline: 1.0151x; 1.0151x over previous
#include <cuda_runtime.h>
#include <cuda_fp16.h>
#include <math.h>
#include <stdint.h>

#define Bsz 4
#define Lseq 2048
#define Dmodel 1024
#define Hheads 16
#define DffDim 4096
#define MAXDIST 512
#define HDdim 64
#define Mrows (Bsz*Lseq)

// Scratch (allocation-free rule: __device__ globals)
__device__ __half h_x   [Mrows*Dmodel];
__device__ __half h_wqkv[Dmodel*3*Dmodel];
__device__ __half h_wout[Dmodel*Dmodel];
__device__ __half h_wff1[Dmodel*DffDim];
__device__ __half h_wff2[DffDim*Dmodel];
__device__ __half h_qkv [Mrows*3*Dmodel];
__device__ __half h_ctx [Mrows*Dmodel];
__device__ __half h_x1  [Mrows*Dmodel];
__device__ __half h_hb  [Mrows*DffDim];
__device__ __half h_tmp [Mrows*Dmodel];

// ---------------------------------------------------------------------------
__device__ __forceinline__ uint32_t s2u(const void* p) {
    uint32_t a;
    asm("{ .reg .u64 t; cvta.to.shared.u64 t, %1; cvt.u32.u64 %0, t; }"
        : "=r"(a) : "l"(p));
    return a;
}
__device__ __forceinline__ void ldsm4(uint32_t* r, uint32_t a) {
    asm volatile("ldmatrix.sync.aligned.m8n8.x4.shared.b16 {%0,%1,%2,%3}, [%4];"
                 : "=r"(r[0]), "=r"(r[1]), "=r"(r[2]), "=r"(r[3]) : "r"(a));
}
__device__ __forceinline__ void ldsm4t(uint32_t* r, uint32_t a) {
    asm volatile("ldmatrix.sync.aligned.m8n8.x4.trans.shared.b16 {%0,%1,%2,%3}, [%4];"
                 : "=r"(r[0]), "=r"(r[1]), "=r"(r[2]), "=r"(r[3]) : "r"(a));
}
__device__ __forceinline__ void mma16(float* c, const uint32_t* a,
                                      uint32_t b0, uint32_t b1) {
    asm volatile(
        "mma.sync.aligned.m16n8k16.row.col.f32.f16.f16.f32 "
        "{%0,%1,%2,%3}, {%4,%5,%6,%7}, {%8,%9}, {%0,%1,%2,%3};"
        : "+f"(c[0]), "+f"(c[1]), "+f"(c[2]), "+f"(c[3])
        : "r"(a[0]), "r"(a[1]), "r"(a[2]), "r"(a[3]), "r"(b0), "r"(b1));
}
#define CPA16(dst, src) \
    asm volatile("cp.async.cg.shared.global [%0], [%1], 16;" :: "r"(dst), "l"(src))
#define CPA_COMMIT() asm volatile("cp.async.commit_group;")

// exact GELU via single-poly erff
__device__ __forceinline__ float gelu_f(float v) {
    return 0.5f * v * (1.f + erff(v * 0.70710678118654752f));
}

// ---------------------------------------------------------------------------
// Fused fp32 -> fp16 conversion of x + 4 weight matrices (one launch).
// ---------------------------------------------------------------------------
#define CN0 (Mrows*Dmodel/4)
#define CN1 (Dmodel*3*Dmodel/4)
#define CN2 (Dmodel*Dmodel/4)
#define CN3 (Dmodel*DffDim/4)
#define CN4 (DffDim*Dmodel/4)
#define CNT (CN0+CN1+CN2+CN3+CN4)

__global__ void cvt_all(const float4* __restrict__ a0, __half2* __restrict__ d0,
                        const float4* __restrict__ a1, __half2* __restrict__ d1,
                        const float4* __restrict__ a2, __half2* __restrict__ d2,
                        const float4* __restrict__ a3, __half2* __restrict__ d3,
                        const float4* __restrict__ a4, __half2* __restrict__ d4)
{
    int j = blockIdx.x*256 + threadIdx.x;
    const float4* s; __half2* d;
    if (j < CN0) { s = a0; d = d0; }
    else { j -= CN0;
    if (j < CN1) { s = a1; d = d1; }
    else { j -= CN1;
    if (j < CN2) { s = a2; d = d2; }
    else { j -= CN2;
    if (j < CN3) { s = a3; d = d3; }
    else { j -= CN3; s = a4; d = d4; } } } }
    float4 v = s[j];
    d[2*j  ] = __floats2half2_rn(v.x, v.y);
    d[2*j+1] = __floats2half2_rn(v.z, v.w);
}

// ---------------------------------------------------------------------------
// fp16 tensor-core GEMM v3: C[M,N] = A[M,K] @ B[K,N].
// 64x128 CTA tile, 128 threads (4 warps = 2m x 2n, warp tile 32x64),
// BK=64, 3-stage cp.async (24KB/stage, 72KB/CTA) -> 3 CTAs/SM: three
// independent barrier domains per SM keep the tensor pipe fed across
// each CTA's wait_group+syncthreads.
// EPI: 0 none, 1 +bias(f32)+res(fp16), 2 +bias then exact GELU.
// OUTH: 1 -> fp16 out, 0 -> fp32 out.
// ---------------------------------------------------------------------------
#define STG_BYTES 24576
#define G_SMEM (3*STG_BYTES)

template<int EPI, int OUTH>
__global__ __launch_bounds__(128, 3)
void gemm_f16(const __half* __restrict__ A, const __half* __restrict__ B,
              float* __restrict__ Cf, __half* __restrict__ Ch,
              int M, int N, int K,
              const float* __restrict__ bias, const __half* __restrict__ res)
{
    extern __shared__ char smem[];
    const uint32_t sb = s2u(smem);
    const int tid = threadIdx.x, wid = tid >> 5, lane = tid & 31;
    const int m0 = blockIdx.y*64, n0 = blockIdx.x*128;
    const int KT = K >> 6;
    const int wm = (wid & 1)*32, wn = (wid >> 1)*64;
    const int r = lane >> 2, cc = lane & 3;
    const int l7 = lane & 7, l15 = lane & 15, lh = lane >> 4;
    const int cbb = (wn >> 3);   // B chunk base for this warp

    auto loadAB = [&](int kt, int s) {
        const uint32_t stA = sb + s*STG_BYTES;          // A: 64 rows x 128B
        const uint32_t stB = stA + 8192;                // B: 64 k-rows x 256B
#pragma unroll
        for (int i = 0; i < 4; i++) {                   // A: 512 chunks
            int idx = tid + i*128;
            int row = idx >> 3, ch = idx & 7;
            CPA16(stA + row*128 + ((ch ^ (row & 7)) << 4),
                  A + (size_t)(m0 + row)*K + kt*64 + ch*8);
        }
#pragma unroll
        for (int i = 0; i < 8; i++) {                   // B: 1024 chunks
            int idx = tid + i*128;
            int k = idx >> 4, ch = idx & 15;
            CPA16(stB + k*256 + ((ch ^ (k & 7)) << 4),
                  B + (size_t)(kt*64 + k)*N + n0 + ch*8);
        }
    };

    float acc[2][8][4];
#pragma unroll
    for (int mi = 0; mi < 2; mi++)
#pragma unroll
        for (int ni = 0; ni < 8; ni++)
#pragma unroll
            for (int q = 0; q < 4; q++) acc[mi][ni][q] = 0.f;

    loadAB(0, 0); CPA_COMMIT();
    loadAB(1, 1); CPA_COMMIT();

    for (int kt = 0; kt < KT; kt++) {
        // leading sync covers RAW (stage kt ready) + WAR (stage (kt+2)%3 free)
        if (kt + 1 < KT) asm volatile("cp.async.wait_group 1;");
        else             asm volatile("cp.async.wait_group 0;");
        __syncthreads();

        if (kt + 2 < KT) {
            loadAB(kt + 2, (kt + 2) % 3);
            CPA_COMMIT();
        }

        const uint32_t stA = sb + (kt % 3)*STG_BYTES;
        const uint32_t stB = stA + 8192;
        const uint32_t aBase = stA + (wm + l15)*128;
        const uint32_t bRow  = stB + l15*256;

#pragma unroll
        for (int ks = 0; ks < 4; ks++) {
            uint32_t af[2][4];
#pragma unroll
            for (int mi = 0; mi < 2; mi++)
                ldsm4(af[mi], aBase + mi*16*128 + (((ks*2 + lh) ^ l7) << 4));
#pragma unroll
            for (int p = 0; p < 4; p++) {
                uint32_t bf[4];
                ldsm4t(bf, bRow + ks*16*256 + (((cbb + p*2 + lh) ^ l7) << 4));
#pragma unroll
                for (int mi = 0; mi < 2; mi++) {
                    mma16(acc[mi][2*p  ], af[mi], bf[0], bf[1]);
                    mma16(acc[mi][2*p+1], af[mi], bf[2], bf[3]);
                }
            }
        }
    }

    // Epilogue (registers only)
#pragma unroll
    for (int ni = 0; ni < 8; ni++) {
        const int col = n0 + wn + ni*8 + 2*cc;
        float b0 = 0.f, b1 = 0.f;
        if (EPI != 0) { b0 = bias[col]; b1 = bias[col + 1]; }
#pragma unroll
        for (int mi = 0; mi < 2; mi++) {
#pragma unroll
            for (int hh = 0; hh < 2; hh++) {
                const int rr = m0 + wm + mi*16 + r + hh*8;
                float v0 = acc[mi][ni][2*hh    ];
                float v1 = acc[mi][ni][2*hh + 1];
                if (EPI != 0) { v0 += b0; v1 += b1; }
                if (EPI == 1) {
                    float2 rv = __half22float2(
                        *(const __half2*)&res[(size_t)rr*N + col]);
                    v0 += rv.x; v1 += rv.y;
                }
                if (EPI == 2) {
                    v0 = gelu_f(v0);
                    v1 = gelu_f(v1);
                }
                if (OUTH)
                    *(__half2*)&Ch[(size_t)rr*N + col] = __floats2half2_rn(v0, v1);
                else
                    *(float2*)&Cf[(size_t)rr*N + col] = make_float2(v0, v1);
            }
        }
    }
}

// ---------------------------------------------------------------------------
// fp16 flash attention (unchanged): 256 thr / 8 warps, 128-row Q tile,
// double-buffered cp.async KV, fp32 online softmax.
// ---------------------------------------------------------------------------
#define FA_SMEM (68*1024)

__global__ __launch_bounds__(256)
void flash_attn_f16(const __half* __restrict__ qkv,
                    const float* __restrict__ bias_table,
                    __half* __restrict__ ctx)
{
    extern __shared__ char smem[];
    const uint32_t Qb = s2u(smem);
    const uint32_t Kb0 = Qb + 16384;
    const uint32_t Vb0 = Qb + 32768;
    const uint32_t Pb  = Qb + 49152;
    float* Bias = (float*)(smem + 65536);

    const int qt = blockIdx.x, bh = blockIdx.y;
    const int b = bh >> 4, h = bh & 15;
    const int tid = threadIdx.x;
    const int wid = tid >> 5, lane = tid & 31;
    const int r = lane >> 2, cc = lane & 3;
    const int l7 = lane & 7, l15 = lane & 15, lh = lane >> 4;
    const int q0 = qt*128, wr = wid*16;
    const size_t rs = 3*Dmodel;
    const __half* base = qkv + (size_t)(b*Lseq)*rs + h*HDdim;

    for (int i = tid; i < 2*MAXDIST-1; i += 256)
        Bias[i] = __ldg(&bias_table[(size_t)i*Hheads + h]);

#pragma unroll
    for (int i = 0; i < 4; i++) {
        int idx = tid + i*256;
        int row = idx >> 3, ch = idx & 7;
        CPA16(Qb + row*128 + ((ch ^ (row & 7)) << 4),
              base + (size_t)(q0 + row)*rs + ch*8);
    }
    CPA_COMMIT();

    auto loadKV = [&](int kt, int s) {
        const int k0 = kt*64;
        const uint32_t Kb = Kb0 + s*8192;
        const uint32_t Vb = Vb0 + s*8192;
#pragma unroll
        for (int i = 0; i < 2; i++) {
            int idx = tid + i*256;
            int row = idx >> 3, ch = idx & 7;
            const __half* gk = base + (size_t)(k0 + row)*rs + Dmodel + ch*8;
            uint32_t sw = ((ch ^ (row & 7)) << 4);
            CPA16(Kb + row*128 + sw, gk);
            CPA16(Vb + row*128 + sw, gk + Dmodel);
        }
    };

    loadKV(0, 0);
    CPA_COMMIT();
    asm volatile("cp.async.wait_group 1;");
    __syncthreads();

    uint32_t qa[4][4];
#pragma unroll
    for (int ks = 0; ks < 4; ks++) {
        int row = wr + l15;
        ldsm4(qa[ks], Qb + row*128 + (((ks*2 + lh) ^ l7) << 4));
    }

    float oacc[8][4];
#pragma unroll
    for (int nt = 0; nt < 8; nt++)
#pragma unroll
        for (int q = 0; q < 4; q++) oacc[nt][q] = 0.f;
    float m0v = -1e30f, m1v = -1e30f, l0 = 0.f, l1 = 0.f;
    const float scale = 0.125f;
    const int qg0 = q0 + wr + r, qg1 = qg0 + 8;
    const int KT = Lseq/64;

    for (int kt = 0; kt < KT; kt++) {
        const int s = kt & 1;
        if (kt + 1 < KT) {
            loadKV(kt + 1, s ^ 1);
            CPA_COMMIT();
            asm volatile("cp.async.wait_group 1;");
        } else {
            asm volatile("cp.async.wait_group 0;");
        }
        __syncthreads();

        const uint32_t Kb = Kb0 + s*8192;
        const uint32_t Vb = Vb0 + s*8192;
        const int k0 = kt*64;

        float sacc[8][4];
#pragma unroll
        for (int nt = 0; nt < 8; nt++)
#pragma unroll
            for (int q = 0; q < 4; q++) sacc[nt][q] = 0.f;
#pragma unroll
        for (int ks = 0; ks < 4; ks++) {
#pragma unroll
            for (int np = 0; np < 4; np++) {
                int key = (np*2 + lh)*8 + l7;
                int ch = ks*2 + ((lane >> 3) & 1);
                uint32_t bf[4];
                ldsm4(bf, Kb + key*128 + ((ch ^ l7) << 4));
                mma16(sacc[2*np  ], qa[ks], bf[0], bf[1]);
                mma16(sacc[2*np+1], qa[ks], bf[2], bf[3]);
            }
        }

        float rmax0 = -1e30f, rmax1 = -1e30f;
#pragma unroll
        for (int nt = 0; nt < 8; nt++) {
            const int kg = k0 + nt*8 + 2*cc;
            int i00 = min(max(kg     - qg0 + (MAXDIST-1), 0), 2*MAXDIST-2);
            int i01 = min(max(kg + 1 - qg0 + (MAXDIST-1), 0), 2*MAXDIST-2);
            int i10 = min(max(kg     - qg1 + (MAXDIST-1), 0), 2*MAXDIST-2);
            int i11 = min(max(kg + 1 - qg1 + (MAXDIST-1), 0), 2*MAXDIST-2);
            sacc[nt][0] = fmaf(sacc[nt][0], scale, Bias[i00]);
            sacc[nt][1] = fmaf(sacc[nt][1], scale, Bias[i01]);
            sacc[nt][2] = fmaf(sacc[nt][2], scale, Bias[i10]);
            sacc[nt][3] = fmaf(sacc[nt][3], scale, Bias[i11]);
            rmax0 = fmaxf(rmax0, fmaxf(sacc[nt][0], sacc[nt][1]));
            rmax1 = fmaxf(rmax1, fmaxf(sacc[nt][2], sacc[nt][3]));
        }
#pragma unroll
        for (int o = 1; o <= 2; o <<= 1) {
            rmax0 = fmaxf(rmax0, __shfl_xor_sync(0xffffffffu, rmax0, o));
            rmax1 = fmaxf(rmax1, __shfl_xor_sync(0xffffffffu, rmax1, o));
        }
        const float mn0 = fmaxf(m0v, rmax0);
        const float mn1 = fmaxf(m1v, rmax1);
        const float corr0 = __expf(m0v - mn0);
        const float corr1 = __expf(m1v - mn1);
        m0v = mn0; m1v = mn1;

        float rsum0 = 0.f, rsum1 = 0.f;
#pragma unroll
        for (int nt = 0; nt < 8; nt++) {
            float p00 = __expf(sacc[nt][0] - mn0);
            float p01 = __expf(sacc[nt][1] - mn0);
            float p10 = __expf(sacc[nt][2] - mn1);
            float p11 = __expf(sacc[nt][3] - mn1);
            rsum0 += p00 + p01;
            rsum1 += p10 + p11;
            uint32_t sw = ((nt ^ r) << 4) + 4*cc;
            *(__half2*)(smem + (Pb - Qb) + (wr + r    )*128 + sw) = __floats2half2_rn(p00, p01);
            *(__half2*)(smem + (Pb - Qb) + (wr + r + 8)*128 + sw) = __floats2half2_rn(p10, p11);
        }
#pragma unroll
        for (int o = 1; o <= 2; o <<= 1) {
            rsum0 += __shfl_xor_sync(0xffffffffu, rsum0, o);
            rsum1 += __shfl_xor_sync(0xffffffffu, rsum1, o);
        }
        l0 = l0*corr0 + rsum0;
        l1 = l1*corr1 + rsum1;
#pragma unroll
        for (int nt = 0; nt < 8; nt++) {
            oacc[nt][0] *= corr0; oacc[nt][1] *= corr0;
            oacc[nt][2] *= corr1; oacc[nt][3] *= corr1;
        }
        __syncwarp();

#pragma unroll
        for (int ks = 0; ks < 4; ks++) {
            uint32_t pf[4];
            {
                int row = wr + l15;
                ldsm4(pf, Pb + row*128 + (((ks*2 + lh) ^ l7) << 4));
            }
#pragma unroll
            for (int p = 0; p < 4; p++) {
                int kk = ks*16 + l15;
                int ch = p*2 + lh;
                uint32_t bf[4];
                ldsm4t(bf, Vb + kk*128 + ((ch ^ l7) << 4));
                mma16(oacc[2*p  ], pf, bf[0], bf[1]);
                mma16(oacc[2*p+1], pf, bf[2], bf[3]);
            }
        }
        __syncthreads();
    }

    const float inv0 = 1.f / l0;
    const float inv1 = 1.f / l1;
    __half* c0p = ctx + (size_t)(b*Lseq + qg0)*Dmodel + h*HDdim;
    __half* c1p = ctx + (size_t)(b*Lseq + qg1)*Dmodel + h*HDdim;
#pragma unroll
    for (int nt = 0; nt < 8; nt++) {
        const int col = nt*8 + 2*cc;
        *(__half2*)&c0p[col] = __floats2half2_rn(oacc[nt][0]*inv0, oacc[nt][1]*inv0);
        *(__half2*)&c1p[col] = __floats2half2_rn(oacc[nt][2]*inv1, oacc[nt][3]*inv1);
    }
}

// ---------------------------------------------------------------------------
// LayerNorm over rows of 1024, fp16 input; optional fp32 and fp16 outputs.
// ---------------------------------------------------------------------------
__global__ __launch_bounds__(256)
void ln_kernel(const __half* __restrict__ in, const float* __restrict__ gamma,
               const float* __restrict__ beta, float* __restrict__ outf,
               __half* __restrict__ out16)
{
    __shared__ float red[16];
    const int row = blockIdx.x;
    const int tid = threadIdx.x;
    const __half2* ip = (const __half2*)(in + (size_t)row*Dmodel);
    float2 fa = __half22float2(ip[2*tid]);
    float2 fb = __half22float2(ip[2*tid+1]);
    float s  = fa.x + fa.y + fb.x + fb.y;
    float sq = fa.x*fa.x + fa.y*fa.y + fb.x*fb.x + fb.y*fb.y;
#pragma unroll
    for (int o = 16; o >= 1; o >>= 1) {
        s  += __shfl_xor_sync(0xffffffffu, s,  o);
        sq += __shfl_xor_sync(0xffffffffu, sq, o);
    }
    const int wid = tid >> 5, lane = tid & 31;
    if (lane == 0) { red[wid] = s; red[wid+8] = sq; }
    __syncthreads();
    if (tid < 32) {
        float s2 = (lane < 8) ? red[lane]   : 0.f;
        float q2 = (lane < 8) ? red[lane+8] : 0.f;
#pragma unroll
        for (int o = 4; o >= 1; o >>= 1) {
            s2 += __shfl_xor_sync(0xffffffffu, s2, o);
            q2 += __shfl_xor_sync(0xffffffffu, q2, o);
        }
        if (lane == 0) { red[0] = s2; red[1] = q2; }
    }
    __syncthreads();
    const float mu  = red[0] * (1.f/Dmodel);
    const float var = red[1] * (1.f/Dmodel) - mu*mu;
    const float inv = rsqrtf(var + 1e-5f);
    const float4 g  = ((const float4*)gamma)[tid];
    const float4 be = ((const float4*)beta)[tid];
    float4 o;
    o.x = (fa.x - mu)*inv*g.x + be.x;
    o.y = (fa.y - mu)*inv*g.y + be.y;
    o.z = (fb.x - mu)*inv*g.z + be.z;
    o.w = (fb.y - mu)*inv*g.w + be.w;
    if (outf)
        ((float4*)(outf + (size_t)row*Dmodel))[tid] = o;
    if (out16) {
        __half2* o2 = (__half2*)(out16 + (size_t)row*Dmodel);
        o2[2*tid  ] = __floats2half2_rn(o.x, o.y);
        o2[2*tid+1] = __floats2half2_rn(o.z, o.w);
    }
}

// ---------------------------------------------------------------------------
extern "C" void kernel_launch(void* const* d_in, const int* in_sizes, int n_in,
                              void* d_out, int out_size)
{
    const float* x          = (const float*)d_in[0];
    const float* w_qkv      = (const float*)d_in[1];
    const float* w_out      = (const float*)d_in[2];
    const float* b_out      = (const float*)d_in[3];
    const float* bias_table = (const float*)d_in[4];
    const float* gamma1     = (const float*)d_in[5];
    const float* beta1      = (const float*)d_in[6];
    const float* w_ff1      = (const float*)d_in[7];
    const float* b_ff1      = (const float*)d_in[8];
    const float* w_ff2      = (const float*)d_in[9];
    const float* b_ff2      = (const float*)d_in[10];
    const float* gamma2     = (const float*)d_in[11];
    const float* beta2      = (const float*)d_in[12];
    float* out = (float*)d_out;

    __half *hx, *hwqkv, *hwout, *hwff1, *hwff2, *hqkv, *hctx, *hx1, *hhb, *htmp;
    cudaGetSymbolAddress((void**)&hx,    h_x);
    cudaGetSymbolAddress((void**)&hwqkv, h_wqkv);
    cudaGetSymbolAddress((void**)&hwout, h_wout);
    cudaGetSymbolAddress((void**)&hwff1, h_wff1);
    cudaGetSymbolAddress((void**)&hwff2, h_wff2);
    cudaGetSymbolAddress((void**)&hqkv,  h_qkv);
    cudaGetSymbolAddress((void**)&hctx,  h_ctx);
    cudaGetSymbolAddress((void**)&hx1,   h_x1);
    cudaGetSymbolAddress((void**)&hhb,   h_hb);
    cudaGetSymbolAddress((void**)&htmp,  h_tmp);

    cudaFuncSetAttribute(gemm_f16<0,1>,
                         cudaFuncAttributeMaxDynamicSharedMemorySize, G_SMEM);
    cudaFuncSetAttribute(gemm_f16<1,1>,
                         cudaFuncAttributeMaxDynamicSharedMemorySize, G_SMEM);
    cudaFuncSetAttribute(gemm_f16<2,1>,
                         cudaFuncAttributeMaxDynamicSharedMemorySize, G_SMEM);
    cudaFuncSetAttribute(flash_attn_f16,
                         cudaFuncAttributeMaxDynamicSharedMemorySize, FA_SMEM);

    const int M = Mrows;  // 8192

    // 0. all fp32->fp16 conversions, one launch
    cvt_all<<<CNT/256, 256>>>(
        (const float4*)x,     (__half2*)hx,
        (const float4*)w_qkv, (__half2*)hwqkv,
        (const float4*)w_out, (__half2*)hwout,
        (const float4*)w_ff1, (__half2*)hwff1,
        (const float4*)w_ff2, (__half2*)hwff2);

    // 1. qkv = x @ w_qkv  (fp16 out)
    gemm_f16<0,1><<<dim3(3*Dmodel/128, M/64), 128, G_SMEM>>>(
        hx, hwqkv, nullptr, hqkv, M, 3*Dmodel, Dmodel, nullptr, nullptr);

    // 2. attention -> ctx (fp16)
    flash_attn_f16<<<dim3(Lseq/128, Bsz*Hheads), 256, FA_SMEM>>>(
        hqkv, bias_table, hctx);

    // 3. tmp = ctx @ w_out + b_out + x  (fp16 out, fp16 res)
    gemm_f16<1,1><<<dim3(Dmodel/128, M/64), 128, G_SMEM>>>(
        hctx, hwout, nullptr, htmp, M, Dmodel, Dmodel, b_out, hx);

    // 4. x1 = LN(tmp)  (fp16 out only)
    ln_kernel<<<M, 256>>>(htmp, gamma1, beta1, nullptr, hx1);

    // 5. hb = GELU(x1 @ w_ff1 + b_ff1)  (fp16 out)
    gemm_f16<2,1><<<dim3(DffDim/128, M/64), 128, G_SMEM>>>(
        hx1, hwff1, nullptr, hhb, M, DffDim, Dmodel, b_ff1, nullptr);

    // 6. tmp = hb @ w_ff2 + b_ff2 + x1  (fp16 out, fp16 res)
    gemm_f16<1,1><<<dim3(Dmodel/128, M/64), 128, G_SMEM>>>(
        hhb, hwff2, nullptr, htmp, M, Dmodel, DffDim, b_ff2, hx1);

    // 7. out = LN(tmp)  (fp32 out)
    ln_kernel<<<M, 256>>>(htmp, gamma2, beta2, out, nullptr);
}